// round 2
// baseline (speedup 1.0000x reference)
#include <cuda_runtime.h>
#include <cuda_bf16.h>
#include <mma.h>
#include <math.h>

using namespace nvcuda;

typedef __nv_bfloat16 bf16;

#define CDIM 1024
#define BB   4
#define TT   4096
#define MTOT (BB*TT)      // 16384
#define NSEG 64
#define TSEG 64           // TT/NSEG

// ---------------- scratch (device globals; no allocation allowed) ----------
__device__ bf16  g_hb  [(size_t)MTOT*CDIM];
__device__ bf16  g_xb  [(size_t)MTOT*CDIM];
__device__ bf16  g_Qb  [(size_t)MTOT*CDIM];
__device__ bf16  g_Kb  [(size_t)MTOT*CDIM];
__device__ bf16  g_Vb  [(size_t)MTOT*CDIM];
__device__ bf16  g_Gb  [(size_t)MTOT*CDIM];
__device__ bf16  g_y0b [(size_t)MTOT*CDIM];
__device__ bf16  g_grad[(size_t)MTOT*CDIM];
__device__ bf16  g_outb[(size_t)MTOT*CDIM];
__device__ float g_KA  [(size_t)MTOT*8];
__device__ float g_segsum[(size_t)BB*NSEG*CDIM];
__device__ float g_loss;

// ---------------- LayerNorm + bf16 casts -----------------------------------
__global__ void ln_kernel(const float* __restrict__ x,
                          const float* __restrict__ lng,
                          const float* __restrict__ lnb)
{
    __shared__ float s_sum[8], s_sq[8];
    const int row = blockIdx.x;
    const int tid = threadIdx.x;
    const int lane = tid & 31, warp = tid >> 5;

    float4 v = *((const float4*)(x + (size_t)row*CDIM) + tid);
    float sum = v.x + v.y + v.z + v.w;
    float sq  = v.x*v.x + v.y*v.y + v.z*v.z + v.w*v.w;
    #pragma unroll
    for (int off = 16; off > 0; off >>= 1) {
        sum += __shfl_xor_sync(0xffffffffu, sum, off);
        sq  += __shfl_xor_sync(0xffffffffu, sq,  off);
    }
    if (lane == 0) { s_sum[warp] = sum; s_sq[warp] = sq; }
    __syncthreads();
    if (warp == 0) {
        float a = (lane < 8) ? s_sum[lane] : 0.f;
        float c = (lane < 8) ? s_sq[lane]  : 0.f;
        #pragma unroll
        for (int off = 4; off > 0; off >>= 1) {
            a += __shfl_xor_sync(0xffffffffu, a, off);
            c += __shfl_xor_sync(0xffffffffu, c, off);
        }
        if (lane == 0) { s_sum[0] = a; s_sq[0] = c; }
    }
    __syncthreads();
    const float mu  = s_sum[0] * (1.f/CDIM);
    const float var = s_sq[0]  * (1.f/CDIM) - mu*mu;
    const float rs  = rsqrtf(var + 1e-5f);

    const int c0 = tid * 4;
    float4 gv = *(const float4*)(lng + c0);
    float4 bv = *(const float4*)(lnb + c0);
    float h0 = (v.x - mu)*rs*gv.x + bv.x;
    float h1 = (v.y - mu)*rs*gv.y + bv.y;
    float h2 = (v.z - mu)*rs*gv.z + bv.z;
    float h3 = (v.w - mu)*rs*gv.w + bv.w;
    size_t o = (size_t)row*CDIM + c0;
    *(__nv_bfloat162*)(g_hb + o)     = __floats2bfloat162_rn(h0, h1);
    *(__nv_bfloat162*)(g_hb + o + 2) = __floats2bfloat162_rn(h2, h3);
    *(__nv_bfloat162*)(g_xb + o)     = __floats2bfloat162_rn(v.x, v.y);
    *(__nv_bfloat162*)(g_xb + o + 2) = __floats2bfloat162_rn(v.z, v.w);
}

// ---------------- bf16 WMMA GEMM  (M=16384, N=K=1024) ----------------------
// TRANSB=true : out[m,n] = sum_c A[m,c] * W[n,c]   (W row-major [n][c])
// TRANSB=false: out[m,n] = sum_c A[m,c] * W[c,n]   (W row-major [c][n])
// EPI 0: store bf16.  EPI 1: Ofin = Xres + acc*lsg[n]  (fp32)
#define BM 128
#define BN 128
#define BK 32
#define LDA 40
#define LDBT 40
#define LDBN 136
#define LDCC 132
#define GEMM_SMEM (BM*LDCC*4)   // 67584 bytes (A+B region = 20480 fits inside)

template<bool TRANSB, int EPI>
__global__ void __launch_bounds__(256)
gemm_kernel(const bf16* __restrict__ A, const float* __restrict__ Bw,
            bf16* __restrict__ Obf,
            const float* __restrict__ Xres, const float* __restrict__ lsg,
            float* __restrict__ Ofin)
{
    extern __shared__ char smem[];
    bf16*  As = (bf16*)smem;
    bf16*  Bs = (bf16*)(smem + BM*LDA*2);
    float* Cs = (float*)smem;

    const int m0 = blockIdx.x * BM;
    const int n0 = blockIdx.y * BN;
    const int tid  = threadIdx.x;
    const int warp = tid >> 5;
    const int wm = warp & 3;   // 4 warps in M
    const int wn = warp >> 2;  // 2 warps in N

    wmma::fragment<wmma::accumulator,16,16,16,float> acc[2][4];
    #pragma unroll
    for (int i = 0; i < 2; i++)
        #pragma unroll
        for (int j = 0; j < 4; j++) wmma::fill_fragment(acc[i][j], 0.0f);

    for (int k0 = 0; k0 < CDIM; k0 += BK) {
        // A tile: 128x32 bf16
        #pragma unroll
        for (int g = tid; g < 512; g += 256) {
            int r = g >> 2, c8 = (g & 3) * 8;
            uint4 v = *(const uint4*)(A + (size_t)(m0 + r)*CDIM + k0 + c8);
            *(uint4*)(As + r*LDA + c8) = v;
        }
        if (TRANSB) {
            // Bs[n][k] (col-major for wmma), W row n contiguous in k
            #pragma unroll
            for (int g = tid; g < 1024; g += 256) {
                int n = g >> 3, k4 = (g & 7) * 4;
                float4 v = *(const float4*)(Bw + (size_t)(n0 + n)*CDIM + k0 + k4);
                *(__nv_bfloat162*)(Bs + n*LDBT + k4)     = __floats2bfloat162_rn(v.x, v.y);
                *(__nv_bfloat162*)(Bs + n*LDBT + k4 + 2) = __floats2bfloat162_rn(v.z, v.w);
            }
        } else {
            // Bs[k][n] row-major
            #pragma unroll
            for (int g = tid; g < 1024; g += 256) {
                int k = g >> 5, n4 = (g & 31) * 4;
                float4 v = *(const float4*)(Bw + (size_t)(k0 + k)*CDIM + n0 + n4);
                *(__nv_bfloat162*)(Bs + k*LDBN + n4)     = __floats2bfloat162_rn(v.x, v.y);
                *(__nv_bfloat162*)(Bs + k*LDBN + n4 + 2) = __floats2bfloat162_rn(v.z, v.w);
            }
        }
        __syncthreads();

        #pragma unroll
        for (int kk = 0; kk < BK; kk += 16) {
            wmma::fragment<wmma::matrix_a,16,16,16,bf16,wmma::row_major> af[2];
            #pragma unroll
            for (int i = 0; i < 2; i++)
                wmma::load_matrix_sync(af[i], As + (wm*32 + i*16)*LDA + kk, LDA);
            #pragma unroll
            for (int j = 0; j < 4; j++) {
                if (TRANSB) {
                    wmma::fragment<wmma::matrix_b,16,16,16,bf16,wmma::col_major> bfr;
                    wmma::load_matrix_sync(bfr, Bs + (wn*64 + j*16)*LDBT + kk, LDBT);
                    #pragma unroll
                    for (int i = 0; i < 2; i++)
                        wmma::mma_sync(acc[i][j], af[i], bfr, acc[i][j]);
                } else {
                    wmma::fragment<wmma::matrix_b,16,16,16,bf16,wmma::row_major> bfr;
                    wmma::load_matrix_sync(bfr, Bs + kk*LDBN + wn*64 + j*16, LDBN);
                    #pragma unroll
                    for (int i = 0; i < 2; i++)
                        wmma::mma_sync(acc[i][j], af[i], bfr, acc[i][j]);
                }
            }
        }
        __syncthreads();
    }

    // epilogue via smem staging (known (m,n) coords)
    #pragma unroll
    for (int i = 0; i < 2; i++)
        #pragma unroll
        for (int j = 0; j < 4; j++)
            wmma::store_matrix_sync(Cs + (wm*32 + i*16)*LDCC + wn*64 + j*16,
                                    acc[i][j], LDCC, wmma::mem_row_major);
    __syncthreads();
    #pragma unroll
    for (int g = tid; g < BM*BN; g += 256) {
        int r = g >> 7, cc = g & 127;
        float v = Cs[r*LDCC + cc];
        size_t o = (size_t)(m0 + r)*CDIM + n0 + cc;
        if (EPI == 0) Obf[o] = __float2bfloat16(v);
        else          Ofin[o] = Xres[o] + v * lsg[n0 + cc];
    }
}

// ---------------- KA = K @ A_init   [MTOT x 8] ------------------------------
__global__ void ka_kernel(const float* __restrict__ A_init)
{
    const int m = blockIdx.x * 8 + (threadIdx.x >> 5);
    const int lane = threadIdx.x & 31;
    float acc[8];
    #pragma unroll
    for (int r = 0; r < 8; r++) acc[r] = 0.f;
    const bf16* kr = g_Kb + (size_t)m*CDIM;
    for (int c = lane; c < CDIM; c += 32) {
        float kv = __bfloat162float(kr[c]);
        float4 a0 = *(const float4*)(A_init + c*8);
        float4 a1 = *(const float4*)(A_init + c*8 + 4);
        acc[0] += kv*a0.x; acc[1] += kv*a0.y; acc[2] += kv*a0.z; acc[3] += kv*a0.w;
        acc[4] += kv*a1.x; acc[5] += kv*a1.y; acc[6] += kv*a1.z; acc[7] += kv*a1.w;
    }
    #pragma unroll
    for (int r = 0; r < 8; r++)
        #pragma unroll
        for (int off = 16; off > 0; off >>= 1)
            acc[r] += __shfl_xor_sync(0xffffffffu, acc[r], off);
    if (lane == 0) {
        #pragma unroll
        for (int r = 0; r < 8; r++) g_KA[(size_t)m*8 + r] = acc[r];
    }
}

// ---------------- error / loss / gradient / segment sums -------------------
__global__ void grad_kernel(const float* __restrict__ Binit)
{
    const int c   = blockIdx.x * 256 + threadIdx.x;
    const int seg = blockIdx.y;
    const int b   = blockIdx.z;
    const int lane = threadIdx.x & 31, warp = threadIdx.x >> 5;
    __shared__ float s_l[8];

    float br[8];
    #pragma unroll
    for (int r = 0; r < 8; r++) br[r] = Binit[r*CDIM + c];

    float segacc = 0.f, lsum = 0.f;
    const int t0 = seg * TSEG;
    for (int t = t0; t < t0 + TSEG; t++) {
        size_t m   = (size_t)b*TT + t;
        size_t idx = m*CDIM + c;
        float4 ka0 = __ldg((const float4*)(g_KA + m*8));
        float4 ka1 = __ldg((const float4*)(g_KA + m*8) + 1);
        float low = ka0.x*br[0] + ka0.y*br[1] + ka0.z*br[2] + ka0.w*br[3]
                  + ka1.x*br[4] + ka1.y*br[5] + ka1.z*br[6] + ka1.w*br[7];
        float y0  = __bfloat162float(g_y0b[idx]) + low;
        float err = y0 - __bfloat162float(g_Vb[idx]);
        lsum += err * err;
        bf16 gb = __float2bfloat16(__bfloat162float(g_Kb[idx]) * err);
        g_grad[idx] = gb;
        segacc += __bfloat162float(gb);   // re-rounded so scan matches pass 4c
    }
    g_segsum[((size_t)b*NSEG + seg)*CDIM + c] = segacc;

    #pragma unroll
    for (int off = 16; off > 0; off >>= 1)
        lsum += __shfl_xor_sync(0xffffffffu, lsum, off);
    if (lane == 0) s_l[warp] = lsum;
    __syncthreads();
    if (threadIdx.x == 0) {
        float tot = 0.f;
        #pragma unroll
        for (int w = 0; w < 8; w++) tot += s_l[w];
        atomicAdd(&g_loss, tot);
    }
}

// ---------------- exclusive scan over segments ------------------------------
__global__ void scan_kernel()
{
    const int c = blockIdx.x * 256 + threadIdx.x;
    const int b = blockIdx.y;
    float run = 0.f;
    for (int s = 0; s < NSEG; s++) {
        size_t i = ((size_t)b*NSEG + s)*CDIM + c;
        float v = g_segsum[i];
        g_segsum[i] = run;
        run += v;
    }
}

// ---------------- out = (y0 - Q*lr*shift*ps) * sigmoid(gate) ----------------
__global__ void out_kernel(const float* __restrict__ Binit,
                           const float* __restrict__ log_lr)
{
    const int c   = blockIdx.x * 256 + threadIdx.x;
    const int seg = blockIdx.y;
    const int b   = blockIdx.z;

    float br[8];
    #pragma unroll
    for (int r = 0; r < 8; r++) br[r] = Binit[r*CDIM + c];
    const float lr = fminf(expf(log_lr[c]), 1.0f);

    float run = g_segsum[((size_t)b*NSEG + seg)*CDIM + c];
    const int t0 = seg * TSEG;
    for (int t = t0; t < t0 + TSEG; t++) {
        size_t m   = (size_t)b*TT + t;
        size_t idx = m*CDIM + c;
        float4 ka0 = __ldg((const float4*)(g_KA + m*8));
        float4 ka1 = __ldg((const float4*)(g_KA + m*8) + 1);
        float low = ka0.x*br[0] + ka0.y*br[1] + ka0.z*br[2] + ka0.w*br[3]
                  + ka1.x*br[4] + ka1.y*br[5] + ka1.z*br[6] + ka1.w*br[7];
        float y0 = __bfloat162float(g_y0b[idx]) + low;
        float shift = run;
        run += __bfloat162float(g_grad[idx]);
        float ps = 1.0f / (1.0f + 0.1f * logf((float)(t + 1)));
        float corr = __bfloat162float(g_Qb[idx]) * lr * shift * ps;
        float gpre = __bfloat162float(g_Gb[idx]);
        float gate = 1.0f / (1.0f + __expf(-gpre));
        g_outb[idx] = __float2bfloat16((y0 - corr) * gate);
    }
}

// ---------------- loss helpers ---------------------------------------------
__global__ void zero_loss_kernel() { g_loss = 0.f; }
__global__ void write_loss_kernel(float* __restrict__ out)
{
    out[(size_t)MTOT*CDIM] = g_loss * (1.0f / ((float)MTOT * (float)CDIM));
}

// ---------------- launch ----------------------------------------------------
extern "C" void kernel_launch(void* const* d_in, const int* in_sizes, int n_in,
                              void* d_out, int out_size)
{
    const float* x      = (const float*)d_in[0];
    const float* W0     = (const float*)d_in[1];
    const float* A_init = (const float*)d_in[2];
    const float* B_init = (const float*)d_in[3];
    const float* log_lr = (const float*)d_in[4];
    const float* Wq     = (const float*)d_in[5];
    const float* Wk     = (const float*)d_in[6];
    const float* Wv     = (const float*)d_in[7];
    const float* Wo     = (const float*)d_in[8];
    const float* Wg     = (const float*)d_in[9];
    const float* ln_g   = (const float*)d_in[10];
    const float* ln_b   = (const float*)d_in[11];
    const float* ls_g   = (const float*)d_in[12];
    float* out = (float*)d_out;

    void *p_hb, *p_xb, *p_Qb, *p_Kb, *p_Vb, *p_Gb, *p_y0b, *p_outb;
    cudaGetSymbolAddress(&p_hb,  g_hb);
    cudaGetSymbolAddress(&p_xb,  g_xb);
    cudaGetSymbolAddress(&p_Qb,  g_Qb);
    cudaGetSymbolAddress(&p_Kb,  g_Kb);
    cudaGetSymbolAddress(&p_Vb,  g_Vb);
    cudaGetSymbolAddress(&p_Gb,  g_Gb);
    cudaGetSymbolAddress(&p_y0b, g_y0b);
    cudaGetSymbolAddress(&p_outb,g_outb);

    cudaFuncSetAttribute(gemm_kernel<true, 0>, cudaFuncAttributeMaxDynamicSharedMemorySize, GEMM_SMEM);
    cudaFuncSetAttribute(gemm_kernel<false,0>, cudaFuncAttributeMaxDynamicSharedMemorySize, GEMM_SMEM);
    cudaFuncSetAttribute(gemm_kernel<true, 1>, cudaFuncAttributeMaxDynamicSharedMemorySize, GEMM_SMEM);

    zero_loss_kernel<<<1, 1>>>();

    ln_kernel<<<MTOT, 256>>>(x, ln_g, ln_b);

    dim3 gGemm(MTOT/BM, CDIM/BN);
    gemm_kernel<true,0><<<gGemm, 256, GEMM_SMEM>>>((const bf16*)p_hb, Wq, (bf16*)p_Qb, nullptr, nullptr, nullptr);
    gemm_kernel<true,0><<<gGemm, 256, GEMM_SMEM>>>((const bf16*)p_hb, Wk, (bf16*)p_Kb, nullptr, nullptr, nullptr);
    gemm_kernel<true,0><<<gGemm, 256, GEMM_SMEM>>>((const bf16*)p_hb, Wv, (bf16*)p_Vb, nullptr, nullptr, nullptr);
    gemm_kernel<true,0><<<gGemm, 256, GEMM_SMEM>>>((const bf16*)p_xb, Wg, (bf16*)p_Gb, nullptr, nullptr, nullptr);

    ka_kernel<<<MTOT/8, 256>>>(A_init);

    gemm_kernel<false,0><<<gGemm, 256, GEMM_SMEM>>>((const bf16*)p_Kb, W0, (bf16*)p_y0b, nullptr, nullptr, nullptr);

    dim3 gSeg(CDIM/256, NSEG, BB);
    grad_kernel<<<gSeg, 256>>>(B_init);
    scan_kernel<<<dim3(CDIM/256, BB), 256>>>();
    out_kernel<<<gSeg, 256>>>(B_init, log_lr);

    gemm_kernel<true,1><<<gGemm, 256, GEMM_SMEM>>>((const bf16*)p_outb, Wo, nullptr, x, ls_g, out);

    if (out_size > MTOT*CDIM)
        write_loss_kernel<<<1, 1>>>(out);
}

// round 6
// speedup vs baseline: 1.3617x; 1.3617x over previous
#include <cuda_runtime.h>
#include <cuda_bf16.h>
#include <math.h>
#include <stdint.h>

typedef __nv_bfloat16 bf16;

#define CDIM 1024
#define BB   4
#define TT   4096
#define MTOT (BB*TT)      // 16384
#define NSEG 64
#define TSEG 64           // TT/NSEG

// ---------------- scratch (device globals; no allocation allowed) ----------
__device__ bf16  g_hb  [(size_t)MTOT*CDIM];
__device__ bf16  g_xb  [(size_t)MTOT*CDIM];
__device__ bf16  g_Qb  [(size_t)MTOT*CDIM];
__device__ bf16  g_Kb  [(size_t)MTOT*CDIM];
__device__ bf16  g_Vb  [(size_t)MTOT*CDIM];
__device__ bf16  g_Gb  [(size_t)MTOT*CDIM];
__device__ bf16  g_y0b [(size_t)MTOT*CDIM];
__device__ bf16  g_grad[(size_t)MTOT*CDIM];
__device__ bf16  g_outb[(size_t)MTOT*CDIM];
__device__ float g_KA  [(size_t)MTOT*8];
__device__ float g_segsum[(size_t)BB*NSEG*CDIM];
__device__ float g_loss;
// bf16 weights (pre-converted once per launch)
__device__ bf16  g_Wqb[(size_t)CDIM*CDIM];
__device__ bf16  g_Wkb[(size_t)CDIM*CDIM];
__device__ bf16  g_Wvb[(size_t)CDIM*CDIM];
__device__ bf16  g_Wgb[(size_t)CDIM*CDIM];
__device__ bf16  g_Wob[(size_t)CDIM*CDIM];
__device__ bf16  g_W0t[(size_t)CDIM*CDIM];   // W0 transposed: W0t[d][c] = W0[c][d]

// ============================================================================
// helpers
// ============================================================================
__device__ __forceinline__ uint32_t smem_u32(const void* p) {
    return (uint32_t)__cvta_generic_to_shared(p);
}
__device__ __forceinline__ void cp16(uint32_t dst, const void* src) {
    asm volatile("cp.async.cg.shared.global [%0], [%1], 16;\n" :: "r"(dst), "l"(src));
}
#define CP_COMMIT() asm volatile("cp.async.commit_group;\n" ::: "memory")
#define CP_WAIT1()  asm volatile("cp.async.wait_group 1;\n" ::: "memory")

__device__ __forceinline__ void ldsm4(uint32_t& r0, uint32_t& r1, uint32_t& r2,
                                      uint32_t& r3, uint32_t addr) {
    asm volatile("ldmatrix.sync.aligned.m8n8.x4.shared.b16 {%0,%1,%2,%3}, [%4];"
                 : "=r"(r0), "=r"(r1), "=r"(r2), "=r"(r3) : "r"(addr));
}
__device__ __forceinline__ void mma16816(float* c, const uint32_t* a,
                                         uint32_t b0, uint32_t b1) {
    asm volatile(
        "mma.sync.aligned.m16n8k16.row.col.f32.bf16.bf16.f32 "
        "{%0,%1,%2,%3}, {%4,%5,%6,%7}, {%8,%9}, {%0,%1,%2,%3};"
        : "+f"(c[0]), "+f"(c[1]), "+f"(c[2]), "+f"(c[3])
        : "r"(a[0]), "r"(a[1]), "r"(a[2]), "r"(a[3]), "r"(b0), "r"(b1));
}

// ============================================================================
// Weight conversion kernels
// ============================================================================
__global__ void cvt_w_kernel(const float* __restrict__ W, bf16* __restrict__ Wb)
{
    size_t i = ((size_t)blockIdx.x * 256 + threadIdx.x) * 4;
    float4 v = *(const float4*)(W + i);
    *(__nv_bfloat162*)(Wb + i)     = __floats2bfloat162_rn(v.x, v.y);
    *(__nv_bfloat162*)(Wb + i + 2) = __floats2bfloat162_rn(v.z, v.w);
}

__global__ void w0t_kernel(const float* __restrict__ W, bf16* __restrict__ Wt)
{
    __shared__ float t[32][33];
    int tx = threadIdx.x, ty = threadIdx.y;
    int x = blockIdx.x * 32 + tx, y = blockIdx.y * 32 + ty;
    #pragma unroll
    for (int j = 0; j < 32; j += 8)
        t[ty + j][tx] = W[(size_t)(y + j) * CDIM + x];
    __syncthreads();
    int x2 = blockIdx.y * 32 + tx, y2 = blockIdx.x * 32 + ty;
    #pragma unroll
    for (int j = 0; j < 32; j += 8)
        Wt[(size_t)(y2 + j) * CDIM + x2] = __float2bfloat16(t[tx][ty + j]);
}

// ============================================================================
// LayerNorm + bf16 casts
// ============================================================================
__global__ void ln_kernel(const float* __restrict__ x,
                          const float* __restrict__ lng,
                          const float* __restrict__ lnb)
{
    __shared__ float s_sum[8], s_sq[8];
    const int row = blockIdx.x;
    const int tid = threadIdx.x;
    const int lane = tid & 31, warp = tid >> 5;

    float4 v = *((const float4*)(x + (size_t)row*CDIM) + tid);
    float sum = v.x + v.y + v.z + v.w;
    float sq  = v.x*v.x + v.y*v.y + v.z*v.z + v.w*v.w;
    #pragma unroll
    for (int off = 16; off > 0; off >>= 1) {
        sum += __shfl_xor_sync(0xffffffffu, sum, off);
        sq  += __shfl_xor_sync(0xffffffffu, sq,  off);
    }
    if (lane == 0) { s_sum[warp] = sum; s_sq[warp] = sq; }
    __syncthreads();
    if (warp == 0) {
        float a = (lane < 8) ? s_sum[lane] : 0.f;
        float c = (lane < 8) ? s_sq[lane]  : 0.f;
        #pragma unroll
        for (int off = 4; off > 0; off >>= 1) {
            a += __shfl_xor_sync(0xffffffffu, a, off);
            c += __shfl_xor_sync(0xffffffffu, c, off);
        }
        if (lane == 0) { s_sum[0] = a; s_sq[0] = c; }
    }
    __syncthreads();
    const float mu  = s_sum[0] * (1.f/CDIM);
    const float var = s_sq[0]  * (1.f/CDIM) - mu*mu;
    const float rs  = rsqrtf(var + 1e-5f);

    const int c0 = tid * 4;
    float4 gv = *(const float4*)(lng + c0);
    float4 bv = *(const float4*)(lnb + c0);
    float h0 = (v.x - mu)*rs*gv.x + bv.x;
    float h1 = (v.y - mu)*rs*gv.y + bv.y;
    float h2 = (v.z - mu)*rs*gv.z + bv.z;
    float h3 = (v.w - mu)*rs*gv.w + bv.w;
    size_t o = (size_t)row*CDIM + c0;
    *(__nv_bfloat162*)(g_hb + o)     = __floats2bfloat162_rn(h0, h1);
    *(__nv_bfloat162*)(g_hb + o + 2) = __floats2bfloat162_rn(h2, h3);
    *(__nv_bfloat162*)(g_xb + o)     = __floats2bfloat162_rn(v.x, v.y);
    *(__nv_bfloat162*)(g_xb + o + 2) = __floats2bfloat162_rn(v.z, v.w);
}

// ============================================================================
// mma.sync bf16 GEMM: out[m,n] = sum_c A[m,c]*Bw[n,c]
// A bf16 [M,1024] row-major, Bw bf16 [1024,1024] row-major ([n][c])
// EPI 0: store bf16.  EPI 1: Ofin = Xres + acc*lsg[n] (fp32)
// ============================================================================
#define GBM 128
#define GBN 256
#define GBK 64
#define GSTG 3
#define LDAP 72                    // padded leading dim (elements)
#define LDBP 72
#define A_STAGE (GBM*LDAP)         // 9216 elements
#define B_STAGE (GBN*LDBP)         // 18432 elements
#define STAGE_ELE (A_STAGE + B_STAGE)
#define GEMM_SMEM (GSTG*STAGE_ELE*2)   // 165888 bytes

__device__ __forceinline__ void load_stage(const bf16* __restrict__ A,
                                           const bf16* __restrict__ Bw,
                                           int m0, int n0, int k0,
                                           bf16* sA, bf16* sB, int tid)
{
    uint32_t aB = smem_u32(sA), bB = smem_u32(sB);
    #pragma unroll
    for (int i = 0; i < 4; i++) {
        int idx = tid + i * 256;
        int r = idx >> 3, c = idx & 7;
        cp16(aB + (uint32_t)(r*LDAP + c*8)*2, A + (size_t)(m0 + r)*CDIM + k0 + c*8);
    }
    #pragma unroll
    for (int i = 0; i < 8; i++) {
        int idx = tid + i * 256;
        int r = idx >> 3, c = idx & 7;
        cp16(bB + (uint32_t)(r*LDBP + c*8)*2, Bw + (size_t)(n0 + r)*CDIM + k0 + c*8);
    }
}

template<int EPI>
__global__ void __launch_bounds__(256, 1)
gemm_mma(const bf16* __restrict__ A, const bf16* __restrict__ Bw,
         bf16* __restrict__ Obf,
         const float* __restrict__ Xres, const float* __restrict__ lsg,
         float* __restrict__ Ofin)
{
    extern __shared__ bf16 sm[];
    const int tid = threadIdx.x, lane = tid & 31, warp = tid >> 5;
    const int wm = warp >> 2, wn = warp & 3;       // 2x4 warp grid, 64x64 each
    const int n0 = blockIdx.x * GBN;
    const int m0 = blockIdx.y * GBM;

    float acc[4][8][4];
    #pragma unroll
    for (int mi = 0; mi < 4; mi++)
        #pragma unroll
        for (int ni = 0; ni < 8; ni++)
            #pragma unroll
            for (int j = 0; j < 4; j++) acc[mi][ni][j] = 0.f;

    // per-thread ldmatrix base offsets (element units)
    const int aRowOff = (lane & 15);                    // + mi*16 + wm*64
    const int aKOff   = (lane >> 4) * 8;
    const int bRowOff = ((lane >> 4) * 8 + (lane & 7)); // + nj*16 + wn*64
    const int bKOff   = ((lane >> 3) & 1) * 8;

    load_stage(A, Bw, m0, n0, 0,     sm,             sm + A_STAGE,             tid);
    CP_COMMIT();
    load_stage(A, Bw, m0, n0, GBK,   sm + STAGE_ELE, sm + STAGE_ELE + A_STAGE, tid);
    CP_COMMIT();

    const int NS = CDIM / GBK;   // 16
    #pragma unroll 1
    for (int s = 0; s < NS; s++) {
        CP_WAIT1();
        __syncthreads();
        if (s + 2 < NS) {
            int b = (s + 2) % GSTG;
            load_stage(A, Bw, m0, n0, (s+2)*GBK,
                       sm + b*STAGE_ELE, sm + b*STAGE_ELE + A_STAGE, tid);
        }
        CP_COMMIT();

        const int cb = s % GSTG;
        const uint32_t aBase = smem_u32(sm + cb*STAGE_ELE);
        const uint32_t bBase = smem_u32(sm + cb*STAGE_ELE + A_STAGE);

        #pragma unroll
        for (int kk = 0; kk < 4; kk++) {
            uint32_t ar[4][4];
            #pragma unroll
            for (int mi = 0; mi < 4; mi++)
                ldsm4(ar[mi][0], ar[mi][1], ar[mi][2], ar[mi][3],
                      aBase + (uint32_t)((wm*64 + mi*16 + aRowOff)*LDAP + kk*16 + aKOff)*2);
            uint32_t br[4][4];
            #pragma unroll
            for (int nj = 0; nj < 4; nj++)
                ldsm4(br[nj][0], br[nj][1], br[nj][2], br[nj][3],
                      bBase + (uint32_t)((wn*64 + nj*16 + bRowOff)*LDBP + kk*16 + bKOff)*2);
            #pragma unroll
            for (int mi = 0; mi < 4; mi++)
                #pragma unroll
                for (int ni = 0; ni < 8; ni++)
                    mma16816(acc[mi][ni], ar[mi],
                             br[ni >> 1][(ni & 1)*2], br[ni >> 1][(ni & 1)*2 + 1]);
        }
    }

    // ---- epilogue: direct global stores, coords known per fragment ----
    const int gr = lane >> 2, gc = (lane & 3) * 2;
    #pragma unroll
    for (int mi = 0; mi < 4; mi++) {
        #pragma unroll
        for (int ni = 0; ni < 8; ni++) {
            const float* c = acc[mi][ni];
            int m = m0 + wm*64 + mi*16 + gr;
            int n = n0 + wn*64 + ni*8 + gc;
            size_t o0 = (size_t)m*CDIM + n;
            size_t o1 = (size_t)(m + 8)*CDIM + n;
            if (EPI == 0) {
                *(__nv_bfloat162*)(Obf + o0) = __floats2bfloat162_rn(c[0], c[1]);
                *(__nv_bfloat162*)(Obf + o1) = __floats2bfloat162_rn(c[2], c[3]);
            } else {
                float2 x0 = *(const float2*)(Xres + o0);
                float2 x1 = *(const float2*)(Xres + o1);
                float2 lv = *(const float2*)(lsg + n);
                float2 r0, r1;
                r0.x = x0.x + c[0]*lv.x;  r0.y = x0.y + c[1]*lv.y;
                r1.x = x1.x + c[2]*lv.x;  r1.y = x1.y + c[3]*lv.y;
                *(float2*)(Ofin + o0) = r0;
                *(float2*)(Ofin + o1) = r1;
            }
        }
    }
}

// ============================================================================
// KA = K @ A_init   [MTOT x 8]
// ============================================================================
__global__ void ka_kernel(const float* __restrict__ A_init)
{
    const int m = blockIdx.x * 8 + (threadIdx.x >> 5);
    const int lane = threadIdx.x & 31;
    float acc[8];
    #pragma unroll
    for (int r = 0; r < 8; r++) acc[r] = 0.f;
    const bf16* kr = g_Kb + (size_t)m*CDIM;
    #pragma unroll 4
    for (int c = lane; c < CDIM; c += 32) {
        float kv = __bfloat162float(kr[c]);
        float4 a0 = *(const float4*)(A_init + c*8);
        float4 a1 = *(const float4*)(A_init + c*8 + 4);
        acc[0] += kv*a0.x; acc[1] += kv*a0.y; acc[2] += kv*a0.z; acc[3] += kv*a0.w;
        acc[4] += kv*a1.x; acc[5] += kv*a1.y; acc[6] += kv*a1.z; acc[7] += kv*a1.w;
    }
    #pragma unroll
    for (int r = 0; r < 8; r++)
        #pragma unroll
        for (int off = 16; off > 0; off >>= 1)
            acc[r] += __shfl_xor_sync(0xffffffffu, acc[r], off);
    if (lane == 0) {
        #pragma unroll
        for (int r = 0; r < 8; r++) g_KA[(size_t)m*8 + r] = acc[r];
    }
}

// ============================================================================
// error / loss / gradient / segment sums  (2 channels per thread)
// ============================================================================
__global__ void grad_kernel(const float* __restrict__ Binit)
{
    const int c   = (blockIdx.x * 256 + threadIdx.x) * 2;
    const int seg = blockIdx.y;
    const int b   = blockIdx.z;
    const int lane = threadIdx.x & 31, warp = threadIdx.x >> 5;
    __shared__ float s_l[8];

    float br0[8], br1[8];
    #pragma unroll
    for (int r = 0; r < 8; r++) {
        br0[r] = Binit[r*CDIM + c];
        br1[r] = Binit[r*CDIM + c + 1];
    }

    float sa0 = 0.f, sa1 = 0.f, lsum = 0.f;
    const int t0 = seg * TSEG;
    #pragma unroll 4
    for (int t = t0; t < t0 + TSEG; t++) {
        size_t m   = (size_t)b*TT + t;
        size_t idx = m*CDIM + c;
        float4 ka0 = __ldg((const float4*)(g_KA + m*8));
        float4 ka1 = __ldg((const float4*)(g_KA + m*8) + 1);
        float low0 = ka0.x*br0[0] + ka0.y*br0[1] + ka0.z*br0[2] + ka0.w*br0[3]
                   + ka1.x*br0[4] + ka1.y*br0[5] + ka1.z*br0[6] + ka1.w*br0[7];
        float low1 = ka0.x*br1[0] + ka0.y*br1[1] + ka0.z*br1[2] + ka0.w*br1[3]
                   + ka1.x*br1[4] + ka1.y*br1[5] + ka1.z*br1[6] + ka1.w*br1[7];
        __nv_bfloat162 y0v = *(const __nv_bfloat162*)(g_y0b + idx);
        __nv_bfloat162 vv  = *(const __nv_bfloat162*)(g_Vb  + idx);
        __nv_bfloat162 kv  = *(const __nv_bfloat162*)(g_Kb  + idx);
        float e0 = __bfloat162float(y0v.x) + low0 - __bfloat162float(vv.x);
        float e1 = __bfloat162float(y0v.y) + low1 - __bfloat162float(vv.y);
        lsum += e0*e0 + e1*e1;
        __nv_bfloat162 gb = __floats2bfloat162_rn(__bfloat162float(kv.x)*e0,
                                                  __bfloat162float(kv.y)*e1);
        *(__nv_bfloat162*)(g_grad + idx) = gb;
        sa0 += __bfloat162float(gb.x);     // re-rounded so scan matches out pass
        sa1 += __bfloat162float(gb.y);
    }
    size_t so = ((size_t)b*NSEG + seg)*CDIM + c;
    g_segsum[so]     = sa0;
    g_segsum[so + 1] = sa1;

    #pragma unroll
    for (int off = 16; off > 0; off >>= 1)
        lsum += __shfl_xor_sync(0xffffffffu, lsum, off);
    if (lane == 0) s_l[warp] = lsum;
    __syncthreads();
    if (threadIdx.x == 0) {
        float tot = 0.f;
        #pragma unroll
        for (int w = 0; w < 8; w++) tot += s_l[w];
        atomicAdd(&g_loss, tot);
    }
}

// ---------------- exclusive scan over segments ------------------------------
__global__ void scan_kernel()
{
    const int c = blockIdx.x * 256 + threadIdx.x;
    const int b = blockIdx.y;
    float run = 0.f;
    #pragma unroll 4
    for (int s = 0; s < NSEG; s++) {
        size_t i = ((size_t)b*NSEG + s)*CDIM + c;
        float v = g_segsum[i];
        g_segsum[i] = run;
        run += v;
    }
}

// ---------------- out = (y0 - Q*lr*shift*ps) * sigmoid(gate) ----------------
__global__ void out_kernel(const float* __restrict__ Binit,
                           const float* __restrict__ log_lr)
{
    const int c   = (blockIdx.x * 256 + threadIdx.x) * 2;
    const int seg = blockIdx.y;
    const int b   = blockIdx.z;

    float br0[8], br1[8];
    #pragma unroll
    for (int r = 0; r < 8; r++) {
        br0[r] = Binit[r*CDIM + c];
        br1[r] = Binit[r*CDIM + c + 1];
    }
    const float lr0 = fminf(expf(log_lr[c]),     1.0f);
    const float lr1 = fminf(expf(log_lr[c + 1]), 1.0f);

    size_t so = ((size_t)b*NSEG + seg)*CDIM + c;
    float run0 = g_segsum[so], run1 = g_segsum[so + 1];
    const int t0 = seg * TSEG;
    #pragma unroll 4
    for (int t = t0; t < t0 + TSEG; t++) {
        size_t m   = (size_t)b*TT + t;
        size_t idx = m*CDIM + c;
        float4 ka0 = __ldg((const float4*)(g_KA + m*8));
        float4 ka1 = __ldg((const float4*)(g_KA + m*8) + 1);
        float low0 = ka0.x*br0[0] + ka0.y*br0[1] + ka0.z*br0[2] + ka0.w*br0[3]
                   + ka1.x*br0[4] + ka1.y*br0[5] + ka1.z*br0[6] + ka1.w*br0[7];
        float low1 = ka0.x*br1[0] + ka0.y*br1[1] + ka0.z*br1[2] + ka0.w*br1[3]
                   + ka1.x*br1[4] + ka1.y*br1[5] + ka1.z*br1[6] + ka1.w*br1[7];
        __nv_bfloat162 y0v = *(const __nv_bfloat162*)(g_y0b  + idx);
        __nv_bfloat162 gv  = *(const __nv_bfloat162*)(g_grad + idx);
        __nv_bfloat162 qv  = *(const __nv_bfloat162*)(g_Qb   + idx);
        __nv_bfloat162 gg  = *(const __nv_bfloat162*)(g_Gb   + idx);
        float y00 = __bfloat162float(y0v.x) + low0;
        float y01 = __bfloat162float(y0v.y) + low1;
        float sh0 = run0, sh1 = run1;
        run0 += __bfloat162float(gv.x);
        run1 += __bfloat162float(gv.y);
        float ps = 1.0f / (1.0f + 0.1f * __logf((float)(t + 1)));
        float corr0 = __bfloat162float(qv.x) * lr0 * sh0 * ps;
        float corr1 = __bfloat162float(qv.y) * lr1 * sh1 * ps;
        float gate0 = 1.0f / (1.0f + __expf(-__bfloat162float(gg.x)));
        float gate1 = 1.0f / (1.0f + __expf(-__bfloat162float(gg.y)));
        *(__nv_bfloat162*)(g_outb + idx) =
            __floats2bfloat162_rn((y00 - corr0) * gate0, (y01 - corr1) * gate1);
    }
}

// ---------------- loss helpers ---------------------------------------------
__global__ void zero_loss_kernel() { g_loss = 0.f; }
__global__ void write_loss_kernel(float* __restrict__ out)
{
    out[(size_t)MTOT*CDIM] = g_loss * (1.0f / ((float)MTOT * (float)CDIM));
}

// ============================================================================
// launch
// ============================================================================
extern "C" void kernel_launch(void* const* d_in, const int* in_sizes, int n_in,
                              void* d_out, int out_size)
{
    const float* x      = (const float*)d_in[0];
    const float* W0     = (const float*)d_in[1];
    const float* A_init = (const float*)d_in[2];
    const float* B_init = (const float*)d_in[3];
    const float* log_lr = (const float*)d_in[4];
    const float* Wq     = (const float*)d_in[5];
    const float* Wk     = (const float*)d_in[6];
    const float* Wv     = (const float*)d_in[7];
    const float* Wo     = (const float*)d_in[8];
    const float* Wg     = (const float*)d_in[9];
    const float* ln_g   = (const float*)d_in[10];
    const float* ln_b   = (const float*)d_in[11];
    const float* ls_g   = (const float*)d_in[12];
    float* out = (float*)d_out;

    void *p_hb, *p_xb, *p_Qb, *p_Kb, *p_Vb, *p_Gb, *p_y0b, *p_outb;
    void *p_Wqb, *p_Wkb, *p_Wvb, *p_Wgb, *p_Wob, *p_W0t;
    cudaGetSymbolAddress(&p_hb,  g_hb);
    cudaGetSymbolAddress(&p_xb,  g_xb);
    cudaGetSymbolAddress(&p_Qb,  g_Qb);
    cudaGetSymbolAddress(&p_Kb,  g_Kb);
    cudaGetSymbolAddress(&p_Vb,  g_Vb);
    cudaGetSymbolAddress(&p_Gb,  g_Gb);
    cudaGetSymbolAddress(&p_y0b, g_y0b);
    cudaGetSymbolAddress(&p_outb,g_outb);
    cudaGetSymbolAddress(&p_Wqb, g_Wqb);
    cudaGetSymbolAddress(&p_Wkb, g_Wkb);
    cudaGetSymbolAddress(&p_Wvb, g_Wvb);
    cudaGetSymbolAddress(&p_Wgb, g_Wgb);
    cudaGetSymbolAddress(&p_Wob, g_Wob);
    cudaGetSymbolAddress(&p_W0t, g_W0t);

    cudaFuncSetAttribute(gemm_mma<0>, cudaFuncAttributeMaxDynamicSharedMemorySize, GEMM_SMEM);
    cudaFuncSetAttribute(gemm_mma<1>, cudaFuncAttributeMaxDynamicSharedMemorySize, GEMM_SMEM);

    zero_loss_kernel<<<1, 1>>>();

    // weight conversion (fp32 -> bf16; W0 transposed)
    const int cvtBlocks = (CDIM*CDIM) / (256*4);
    cvt_w_kernel<<<cvtBlocks, 256>>>(Wq, (bf16*)p_Wqb);
    cvt_w_kernel<<<cvtBlocks, 256>>>(Wk, (bf16*)p_Wkb);
    cvt_w_kernel<<<cvtBlocks, 256>>>(Wv, (bf16*)p_Wvb);
    cvt_w_kernel<<<cvtBlocks, 256>>>(Wg, (bf16*)p_Wgb);
    cvt_w_kernel<<<cvtBlocks, 256>>>(Wo, (bf16*)p_Wob);
    w0t_kernel<<<dim3(CDIM/32, CDIM/32), dim3(32, 8)>>>(W0, (bf16*)p_W0t);

    ln_kernel<<<MTOT, 256>>>(x, ln_g, ln_b);

    dim3 gG(CDIM/GBN, MTOT/GBM);   // (4, 128): n fastest -> A-tile L2 reuse within wave
    gemm_mma<0><<<gG, 256, GEMM_SMEM>>>((const bf16*)p_hb, (const bf16*)p_Wqb, (bf16*)p_Qb, nullptr, nullptr, nullptr);
    gemm_mma<0><<<gG, 256, GEMM_SMEM>>>((const bf16*)p_hb, (const bf16*)p_Wkb, (bf16*)p_Kb, nullptr, nullptr, nullptr);
    gemm_mma<0><<<gG, 256, GEMM_SMEM>>>((const bf16*)p_hb, (const bf16*)p_Wvb, (bf16*)p_Vb, nullptr, nullptr, nullptr);
    gemm_mma<0><<<gG, 256, GEMM_SMEM>>>((const bf16*)p_xb, (const bf16*)p_Wgb, (bf16*)p_Gb, nullptr, nullptr, nullptr);

    ka_kernel<<<MTOT/8, 256>>>(A_init);

    gemm_mma<0><<<gG, 256, GEMM_SMEM>>>((const bf16*)p_Kb, (const bf16*)p_W0t, (bf16*)p_y0b, nullptr, nullptr, nullptr);

    dim3 gSeg(CDIM/512, NSEG, BB);
    grad_kernel<<<gSeg, 256>>>(B_init);
    scan_kernel<<<dim3(CDIM/256, BB), 256>>>();
    out_kernel<<<gSeg, 256>>>(B_init, log_lr);

    gemm_mma<1><<<gG, 256, GEMM_SMEM>>>((const bf16*)p_outb, (const bf16*)p_Wob, nullptr, x, ls_g, out);

    if (out_size > MTOT*CDIM)
        write_loss_kernel<<<1, 1>>>(out);
}